// round 13
// baseline (speedup 1.0000x reference)
#include <cuda_runtime.h>
#include <cuda_fp16.h>
#include <cstdint>
#include <math.h>

#define B_ 2
#define S_ 2048
#define D_ 1024
#define H_ 16
#define DK_ 64
#define M_ (B_*S_)
#define NEGINF (-1000000000.0f)

// ---------------------------------------------------------------------------
// Scratch: 48 MiB. Score path (Q, K) hi/lo fp16; value path (V, att) single.
// ---------------------------------------------------------------------------
__device__ __half g_Qh_hi[M_*D_], g_Qh_lo[M_*D_];   // [bh][s][dk]
__device__ __half g_Kh_hi[M_*D_], g_Kh_lo[M_*D_];
__device__ __half g_Vh[M_*D_];
__device__ __half g_att[M_*D_];                     // [m][d] single fp16

// ---------------------------------------------------------------------------
// PTX helpers
// ---------------------------------------------------------------------------
__device__ __forceinline__ uint32_t smem_u32(const void* p) {
    uint32_t a;
    asm("{ .reg .u64 t; cvta.to.shared.u64 t, %1; cvt.u32.u64 %0, t; }" : "=r"(a) : "l"(p));
    return a;
}
__device__ __forceinline__ void ldsm4(uint32_t* r, uint32_t addr) {
    asm volatile("ldmatrix.sync.aligned.m8n8.x4.shared.b16 {%0,%1,%2,%3}, [%4];"
        : "=r"(r[0]), "=r"(r[1]), "=r"(r[2]), "=r"(r[3]) : "r"(addr));
}
__device__ __forceinline__ void ldsm4_t(uint32_t* r, uint32_t addr) {
    asm volatile("ldmatrix.sync.aligned.m8n8.x4.trans.shared.b16 {%0,%1,%2,%3}, [%4];"
        : "=r"(r[0]), "=r"(r[1]), "=r"(r[2]), "=r"(r[3]) : "r"(addr));
}
__device__ __forceinline__ void mma16816(float* d, const uint32_t* a, const uint32_t* b) {
    asm volatile(
        "mma.sync.aligned.m16n8k16.row.col.f32.f16.f16.f32 "
        "{%0,%1,%2,%3}, {%4,%5,%6,%7}, {%8,%9}, {%0,%1,%2,%3};"
        : "+f"(d[0]), "+f"(d[1]), "+f"(d[2]), "+f"(d[3])
        : "r"(a[0]), "r"(a[1]), "r"(a[2]), "r"(a[3]), "r"(b[0]), "r"(b[1]));
}
__device__ __forceinline__ void cpa16(uint32_t s, const void* g) {
    asm volatile("cp.async.cg.shared.global [%0], [%1], 16;" :: "r"(s), "l"(g));
}
#define CPA_COMMIT() asm volatile("cp.async.commit_group;" ::: "memory")
#define CPA_WAIT0()  asm volatile("cp.async.wait_group 0;" ::: "memory")

__device__ __forceinline__ uint32_t packh(float lo, float hi) {
    __half2 h = __floats2half2_rn(lo, hi);
    return *(uint32_t*)&h;
}
__device__ __forceinline__ float hres(float x) {
    return x - __half2float(__float2half_rn(x));
}
__device__ __forceinline__ void splith4(float4 x, uint2& h, uint2& l) {
    h.x = packh(x.x, x.y);  h.y = packh(x.z, x.w);
    l.x = packh(hres(x.x), hres(x.y));
    l.y = packh(hres(x.z), hres(x.w));
}
__device__ __forceinline__ uint2 cvt4(float4 x) {
    uint2 r; r.x = packh(x.x, x.y); r.y = packh(x.z, x.w); return r;
}
__device__ __forceinline__ void sts_split4(__half* hi, __half* lo,
                                           int row, int v, int pad, float4 x) {
    uint2 h, l; splith4(x, h, l);
    *(uint2*)(hi + row*pad + v*4) = h;
    *(uint2*)(lo + row*pad + v*4) = l;
}
__device__ __forceinline__ void sts_cvt4(__half* dst, int row, int v, int pad, float4 x) {
    *(uint2*)(dst + row*pad + v*4) = cvt4(x);
}

// ---------------------------------------------------------------------------
// Projection GEMM: C[m,n] = sum_k A[m,k]*W[n,k] + bias[n]
// 128x256 block, BK=64, 512 threads (16 warps 4m x 4n, warp tile 32x64).
// TERMS=3: A hi/lo, W hi/lo, 3 MMAs (score path).
// TERMS=1: A single, W single, 1 MMA (value path).
// AHALF=1: A is fp16 single in gmem, staged via cp.async (out-proj).
// MODE: 0 fp32 row-major; 1 fp16 hi/lo remap [bh,s,dk]; 2 fp16 single remap.
// ---------------------------------------------------------------------------
#define PPAD 72
#define PASLAB (128*PPAD)               // 9216
#define PWSLAB (256*PPAD)               // 18432
#define PROJ_SMEM3 (2*(2*PASLAB + 2*PWSLAB)*2)   // 221184 B
#define PROJ_SMEM1 (2*(PASLAB + PWSLAB)*2)       // 110592 B

template<int TERMS>
__device__ __forceinline__ void proj_mma_kk(uint32_t stage_u, int kk, int wm, int wn,
                                            int lane, float acc[2][8][4])
{
    constexpr int ASL   = (TERMS == 3) ? 2 : 1;
    constexpr int POFFW = ASL*PASLAB;
    uint32_t ah[2][4], al[2][4];
    #pragma unroll
    for (int mi = 0; mi < 2; mi++) {
        const int r   = wm*32 + mi*16 + (lane & 15);
        const int col = kk*16 + ((lane & 16) ? 8 : 0);
        ldsm4(ah[mi], stage_u + 2*(0*PASLAB + r*PPAD + col));
        if (TERMS == 3) ldsm4(al[mi], stage_u + 2*(1*PASLAB + r*PPAD + col));
    }
    #pragma unroll
    for (int jp = 0; jp < 4; jp++) {
        const int p   = lane >> 3;
        const int r   = wn*64 + jp*16 + ((p >= 2) ? 8 : 0) + (lane & 7);
        const int col = kk*16 + ((p & 1) ? 8 : 0);
        uint32_t th[4], tl[4];
        ldsm4(th, stage_u + 2*(POFFW + r*PPAD + col));
        if (TERMS == 3) ldsm4(tl, stage_u + 2*(POFFW + PWSLAB + r*PPAD + col));
        #pragma unroll
        for (int mi = 0; mi < 2; mi++) {
            mma16816(acc[mi][2*jp], ah[mi], th);
            if (TERMS == 3) {
                mma16816(acc[mi][2*jp], al[mi], th);
                mma16816(acc[mi][2*jp], ah[mi], tl);
            }
            mma16816(acc[mi][2*jp+1], ah[mi], th+2);
            if (TERMS == 3) {
                mma16816(acc[mi][2*jp+1], al[mi], th+2);
                mma16816(acc[mi][2*jp+1], ah[mi], tl+2);
            }
        }
    }
}

template<int MODE, int TERMS, int AHALF>
__device__ __forceinline__ void proj_gemm(const float* __restrict__ Af,
                                          const __half* __restrict__ Ah16,
                                          const float* __restrict__ W,
                                          const float* __restrict__ bias,
                                          float* __restrict__ Cf,
                                          __half* __restrict__ Chi,
                                          __half* __restrict__ Clo)
{
    constexpr int ASL   = (TERMS == 3) ? 2 : 1;
    constexpr int POFFW = ASL*PASLAB;
    constexpr int PSTG  = ASL*PASLAB + ((TERMS == 3) ? 2 : 1)*PWSLAB;

    extern __shared__ __half sm[];
    const uint32_t sb = smem_u32(sm);
    const int tid  = threadIdx.x;
    const int lane = tid & 31;
    const int wid  = tid >> 5;
    const int wm   = wid & 3;
    const int wn   = wid >> 2;
    const int m0 = blockIdx.y * 128;
    const int n0 = blockIdx.x * 256;

    const int frow = tid >> 4;            // 0..31 (+it*32); fp32 float4 loads
    const int fv   = tid & 15;

    float acc[2][8][4];
    #pragma unroll
    for (int mi = 0; mi < 2; mi++)
        #pragma unroll
        for (int nj = 0; nj < 8; nj++)
            #pragma unroll
            for (int e = 0; e < 4; e++) acc[mi][nj][e] = 0.0f;

    float4 pa[4], pw[4];

    // ---- prologue: chunk 0 -> stage 0 ----
    if (AHALF) {
        #pragma unroll
        for (int it = 0; it < 2; it++) {
            const int idx = tid + it*512;          // 0..1023
            const int row = idx >> 3, v = idx & 7;
            cpa16(sb + 2*(row*PPAD + v*8), Ah16 + (size_t)(m0+row)*D_ + v*8);
        }
        CPA_COMMIT();
    } else {
        #pragma unroll
        for (int it = 0; it < 4; it++) {
            const int row = frow + it*32;
            float4 x = *((const float4*)(Af + (size_t)(m0+row)*D_) + fv);
            if (TERMS == 3) sts_split4(sm, sm + PASLAB, row, fv, PPAD, x);
            else            sts_cvt4(sm, row, fv, PPAD, x);
        }
    }
    #pragma unroll
    for (int it = 0; it < 8; it++) {
        const int row = frow + it*32;
        float4 x = *((const float4*)(W + (size_t)(n0+row)*D_) + fv);
        if (TERMS == 3) sts_split4(sm + POFFW, sm + POFFW + PWSLAB, row, fv, PPAD, x);
        else            sts_cvt4(sm + POFFW, row, fv, PPAD, x);
    }
    if (AHALF) CPA_WAIT0();
    __syncthreads();

    for (int c = 0; c < 16; c++) {
        const int cur = c & 1;
        const int nxt = cur ^ 1;
        const uint32_t scur_u = sb + 2*(cur*PSTG);
        const uint32_t snx_u  = sb + 2*(nxt*PSTG);
        __half* snx = sm + nxt*PSTG;
        const int k1 = (c + 1) * 64;
        const bool pf = (c < 15);

        if (pf) {
            if (AHALF) {
                #pragma unroll
                for (int it = 0; it < 2; it++) {
                    const int idx = tid + it*512;
                    const int row = idx >> 3, v = idx & 7;
                    cpa16(snx_u + 2*(row*PPAD + v*8),
                          Ah16 + (size_t)(m0+row)*D_ + k1 + v*8);
                }
                CPA_COMMIT();
            } else {
                #pragma unroll
                for (int it = 0; it < 4; it++) {
                    const int row = frow + it*32;
                    pa[it] = *((const float4*)(Af + (size_t)(m0+row)*D_ + k1) + fv);
                }
            }
        }
        proj_mma_kk<TERMS>(scur_u, 0, wm, wn, lane, acc);
        if (pf) {
            if (!AHALF) {
                #pragma unroll
                for (int it = 0; it < 4; it++) {
                    if (TERMS == 3) sts_split4(snx, snx + PASLAB, frow + it*32, fv, PPAD, pa[it]);
                    else            sts_cvt4(snx, frow + it*32, fv, PPAD, pa[it]);
                }
            }
            #pragma unroll
            for (int it = 0; it < 4; it++) {
                const int row = frow + it*32;
                pw[it] = *((const float4*)(W + (size_t)(n0+row)*D_ + k1) + fv);
            }
        }
        proj_mma_kk<TERMS>(scur_u, 1, wm, wn, lane, acc);
        if (pf) {
            #pragma unroll
            for (int it = 0; it < 4; it++) {
                if (TERMS == 3) sts_split4(snx + POFFW, snx + POFFW + PWSLAB,
                                           frow + it*32, fv, PPAD, pw[it]);
                else            sts_cvt4(snx + POFFW, frow + it*32, fv, PPAD, pw[it]);
            }
            #pragma unroll
            for (int it = 0; it < 4; it++) {
                const int row = frow + (it + 4)*32;
                pw[it] = *((const float4*)(W + (size_t)(n0+row)*D_ + k1) + fv);
            }
        }
        proj_mma_kk<TERMS>(scur_u, 2, wm, wn, lane, acc);
        if (pf) {
            #pragma unroll
            for (int it = 0; it < 4; it++) {
                if (TERMS == 3) sts_split4(snx + POFFW, snx + POFFW + PWSLAB,
                                           frow + (it + 4)*32, fv, PPAD, pw[it]);
                else            sts_cvt4(snx + POFFW, frow + (it + 4)*32, fv, PPAD, pw[it]);
            }
        }
        proj_mma_kk<TERMS>(scur_u, 3, wm, wn, lane, acc);
        if (pf && AHALF) CPA_WAIT0();
        __syncthreads();
    }

    // ---- epilogue ----
    const int g  = lane >> 2;
    const int cc = lane & 3;
    #pragma unroll
    for (int mi = 0; mi < 2; mi++) {
        const int ra = m0 + wm*32 + mi*16 + g;
        const int rb = ra + 8;
        #pragma unroll
        for (int nj = 0; nj < 8; nj++) {
            const int col = n0 + wn*64 + nj*8 + cc*2;
            const float b0 = bias[col], b1 = bias[col+1];
            const float v00 = acc[mi][nj][0] + b0, v01 = acc[mi][nj][1] + b1;
            const float v10 = acc[mi][nj][2] + b0, v11 = acc[mi][nj][3] + b1;
            if (MODE == 0) {
                *(float2*)&Cf[(size_t)ra*D_ + col] = make_float2(v00, v01);
                *(float2*)&Cf[(size_t)rb*D_ + col] = make_float2(v10, v11);
            } else {
                const int h = col >> 6, dk = col & 63;
                const int ba = ra >> 11, sa = ra & (S_-1);
                const int bb = rb >> 11, sb2 = rb & (S_-1);
                const size_t ia = (((size_t)ba*H_ + h)*S_ + sa)*DK_ + dk;
                const size_t ib = (((size_t)bb*H_ + h)*S_ + sb2)*DK_ + dk;
                *(uint32_t*)&Chi[ia] = packh(v00, v01);
                *(uint32_t*)&Chi[ib] = packh(v10, v11);
                if (MODE == 1) {
                    *(uint32_t*)&Clo[ia] = packh(hres(v00), hres(v01));
                    *(uint32_t*)&Clo[ib] = packh(hres(v10), hres(v11));
                }
            }
        }
    }
}

__global__ void __launch_bounds__(512, 1)
qkv_mma_kernel(const float* __restrict__ q, const float* __restrict__ k,
               const float* __restrict__ v,
               const float* __restrict__ Wq, const float* __restrict__ bq,
               const float* __restrict__ Wk, const float* __restrict__ bk,
               const float* __restrict__ Wv, const float* __restrict__ bv)
{
    const int z = blockIdx.z;
    if (z == 0)      proj_gemm<1,3,0>(q, nullptr, Wq, bq, nullptr, g_Qh_hi, g_Qh_lo);
    else if (z == 1) proj_gemm<1,3,0>(k, nullptr, Wk, bk, nullptr, g_Kh_hi, g_Kh_lo);
    else             proj_gemm<2,1,0>(v, nullptr, Wv, bv, nullptr, g_Vh, nullptr);
}

__global__ void __launch_bounds__(512, 1)
out_mma_kernel(const float* __restrict__ Wo, const float* __restrict__ bo,
               float* __restrict__ out)
{
    proj_gemm<0,1,1>(nullptr, g_att, Wo, bo, out, nullptr, nullptr);
}

// ---------------------------------------------------------------------------
// Flash attention. QK 3-term (Q hi/lo x K hi/lo, exact score path);
// PV 1-term (P single x V single). 256 threads, 8 warps x m32 = 256 q rows.
// K hi/lo + V single double-buffered via cp.async. Mask: query rows.
// ---------------------------------------------------------------------------
#define APAD 72
#define AQSLAB (256*APAD)
#define ASLAB  (64*APAD)
#define AKV0   (2*AQSLAB)
// KV slabs: [K0h K0l K1h K1l V0 V1]
#define ATT_SMEM ((2*AQSLAB + 6*ASLAB)*2)   // 129024 B

__global__ void __launch_bounds__(256, 1)
attn_mma_kernel(const int* __restrict__ mask)
{
    extern __shared__ __half sm[];
    const uint32_t sb = smem_u32(sm);
    const int tid  = threadIdx.x;
    const int lane = tid & 31;
    const int wid  = tid >> 5;
    const int g    = lane >> 2;
    const int cc   = lane & 3;

    const int bh = blockIdx.y;
    const int b  = bh >> 4;
    const int h  = bh & 15;
    const int q0 = blockIdx.x * 256;

    const __half* Qhi = g_Qh_hi + (size_t)bh*S_*DK_;
    const __half* Qlo = g_Qh_lo + (size_t)bh*S_*DK_;
    const __half* Khi = g_Kh_hi + (size_t)bh*S_*DK_;
    const __half* Klo = g_Kh_lo + (size_t)bh*S_*DK_;
    const __half* Vp  = g_Vh + (size_t)bh*S_*DK_;
    const int* mp = mask + b*S_;

    // ---- issue KV tile 0 via cp.async; load Q concurrently ----
    {
        #pragma unroll
        for (int i = 0; i < 2; i++) {
            const int idx = tid + i*256;           // 0..511
            const int row = idx >> 3, v = idx & 7;
            const uint32_t so = sb + 2*(AKV0 + row*APAD + v*8);
            const size_t  go = (size_t)row*DK_ + v*8;
            cpa16(so + 2*(0*ASLAB), Khi + go);
            cpa16(so + 2*(1*ASLAB), Klo + go);
            cpa16(so + 2*(4*ASLAB), Vp + go);
        }
        CPA_COMMIT();
    }
    #pragma unroll
    for (int it = 0; it < 8; it++) {
        const int idx = tid + it*256;              // 0..2047
        const int row = idx >> 3, v = idx & 7;
        *(uint4*)(sm + 0      + row*APAD + v*8) =
            *((const uint4*)(Qhi + (size_t)(q0+row)*DK_) + v);
        *(uint4*)(sm + AQSLAB + row*APAD + v*8) =
            *((const uint4*)(Qlo + (size_t)(q0+row)*DK_) + v);
    }
    CPA_WAIT0();
    __syncthreads();

    const int qra0 = q0 + wid*32 + g;
    const int qra1 = qra0 + 16;
    bool msk[2][2];
    msk[0][0] = (mp[qra0] == 0);      msk[0][1] = (mp[qra0 + 8] == 0);
    msk[1][0] = (mp[qra1] == 0);      msk[1][1] = (mp[qra1 + 8] == 0);

    float mr[2][2], lr[2][2];
    #pragma unroll
    for (int mi = 0; mi < 2; mi++) { mr[mi][0] = mr[mi][1] = -1e30f; lr[mi][0] = lr[mi][1] = 0.0f; }

    float oacc[2][8][4];
    #pragma unroll
    for (int mi = 0; mi < 2; mi++)
        #pragma unroll
        for (int nj = 0; nj < 8; nj++)
            #pragma unroll
            for (int e = 0; e < 4; e++) oacc[mi][nj][e] = 0.0f;

    for (int t = 0; t < 32; t++) {
        const int cur = t & 1;
        const int nxt = cur ^ 1;
        const bool pf = (t + 1 < 32);
        const uint32_t kh_u = sb + 2*(AKV0 + (2*cur)*ASLAB);
        const uint32_t kl_u = kh_u + 2*ASLAB;
        const uint32_t v_u  = sb + 2*(AKV0 + (4 + cur)*ASLAB);

        if (pf) {
            const size_t base = (size_t)((t + 1)*64)*DK_;
            #pragma unroll
            for (int i = 0; i < 2; i++) {
                const int idx = tid + i*256;
                const int row = idx >> 3, v = idx & 7;
                const uint32_t so = sb + 2*(AKV0 + row*APAD + v*8);
                const size_t  go = base + (size_t)row*DK_ + v*8;
                cpa16(so + 2*((2*nxt)*ASLAB),   Khi + go);
                cpa16(so + 2*((2*nxt+1)*ASLAB), Klo + go);
                cpa16(so + 2*((4 + nxt)*ASLAB), Vp + go);
            }
            CPA_COMMIT();
        }

        // ---- S = Q K^T (3-term: exact score path) ----
        float sacc[2][8][4];
        #pragma unroll
        for (int mi = 0; mi < 2; mi++)
            #pragma unroll
            for (int nj = 0; nj < 8; nj++)
                #pragma unroll
                for (int e = 0; e < 4; e++) sacc[mi][nj][e] = 0.0f;

        #pragma unroll
        for (int kk = 0; kk < 4; kk++) {
            uint32_t aqh[2][4], aql[2][4];
            #pragma unroll
            for (int mi = 0; mi < 2; mi++) {
                const int r   = wid*32 + mi*16 + (lane & 15);
                const int col = kk*16 + ((lane & 16) ? 8 : 0);
                ldsm4(aqh[mi], sb + 2*(0      + r*APAD + col));
                ldsm4(aql[mi], sb + 2*(AQSLAB + r*APAD + col));
            }
            #pragma unroll
            for (int jp = 0; jp < 4; jp++) {
                const int p   = lane >> 3;
                const int r   = jp*16 + ((p >= 2) ? 8 : 0) + (lane & 7);
                const int col = kk*16 + ((p & 1) ? 8 : 0);
                uint32_t th[4], tl[4];
                ldsm4(th, kh_u + 2*(r*APAD + col));
                ldsm4(tl, kl_u + 2*(r*APAD + col));
                #pragma unroll
                for (int mi = 0; mi < 2; mi++) {
                    mma16816(sacc[mi][2*jp],   aqh[mi], th);
                    mma16816(sacc[mi][2*jp],   aql[mi], th);
                    mma16816(sacc[mi][2*jp],   aqh[mi], tl);
                    mma16816(sacc[mi][2*jp+1], aqh[mi], th+2);
                    mma16816(sacc[mi][2*jp+1], aql[mi], th+2);
                    mma16816(sacc[mi][2*jp+1], aqh[mi], tl+2);
                }
            }
        }

        // ---- mask + online softmax ----
        #pragma unroll
        for (int mi = 0; mi < 2; mi++) {
            if (msk[mi][0]) {
                #pragma unroll
                for (int nj = 0; nj < 8; nj++) { sacc[mi][nj][0] = NEGINF; sacc[mi][nj][1] = NEGINF; }
            }
            if (msk[mi][1]) {
                #pragma unroll
                for (int nj = 0; nj < 8; nj++) { sacc[mi][nj][2] = NEGINF; sacc[mi][nj][3] = NEGINF; }
            }

            float mx0 = -1e30f, mx1 = -1e30f;
            #pragma unroll
            for (int nj = 0; nj < 8; nj++) {
                mx0 = fmaxf(mx0, fmaxf(sacc[mi][nj][0], sacc[mi][nj][1]));
                mx1 = fmaxf(mx1, fmaxf(sacc[mi][nj][2], sacc[mi][nj][3]));
            }
            mx0 = fmaxf(mx0, __shfl_xor_sync(0xffffffffu, mx0, 1));
            mx0 = fmaxf(mx0, __shfl_xor_sync(0xffffffffu, mx0, 2));
            mx1 = fmaxf(mx1, __shfl_xor_sync(0xffffffffu, mx1, 1));
            mx1 = fmaxf(mx1, __shfl_xor_sync(0xffffffffu, mx1, 2));

            const float mn0 = fmaxf(mr[mi][0], mx0);
            const float mn1 = fmaxf(mr[mi][1], mx1);
            const float al0 = __expf(mr[mi][0] - mn0);
            const float al1 = __expf(mr[mi][1] - mn1);
            mr[mi][0] = mn0; mr[mi][1] = mn1;

            float rs0 = 0.0f, rs1 = 0.0f;
            #pragma unroll
            for (int nj = 0; nj < 8; nj++) {
                const float p0 = __expf(sacc[mi][nj][0] - mn0);
                const float p1 = __expf(sacc[mi][nj][1] - mn0);
                const float p2 = __expf(sacc[mi][nj][2] - mn1);
                const float p3 = __expf(sacc[mi][nj][3] - mn1);
                sacc[mi][nj][0] = p0; sacc[mi][nj][1] = p1;
                sacc[mi][nj][2] = p2; sacc[mi][nj][3] = p3;
                rs0 += p0 + p1; rs1 += p2 + p3;
            }
            rs0 += __shfl_xor_sync(0xffffffffu, rs0, 1);
            rs0 += __shfl_xor_sync(0xffffffffu, rs0, 2);
            rs1 += __shfl_xor_sync(0xffffffffu, rs1, 1);
            rs1 += __shfl_xor_sync(0xffffffffu, rs1, 2);
            lr[mi][0] = lr[mi][0]*al0 + rs0;
            lr[mi][1] = lr[mi][1]*al1 + rs1;

            #pragma unroll
            for (int nj = 0; nj < 8; nj++) {
                oacc[mi][nj][0] *= al0; oacc[mi][nj][1] *= al0;
                oacc[mi][nj][2] *= al1; oacc[mi][nj][3] *= al1;
            }
        }

        // ---- O += P V (1-term: P single x V single) ----
        #pragma unroll
        for (int t4 = 0; t4 < 4; t4++) {
            uint32_t pa[2][4];
            #pragma unroll
            for (int mi = 0; mi < 2; mi++) {
                pa[mi][0] = packh(sacc[mi][2*t4][0],   sacc[mi][2*t4][1]);
                pa[mi][1] = packh(sacc[mi][2*t4][2],   sacc[mi][2*t4][3]);
                pa[mi][2] = packh(sacc[mi][2*t4+1][0], sacc[mi][2*t4+1][1]);
                pa[mi][3] = packh(sacc[mi][2*t4+1][2], sacc[mi][2*t4+1][3]);
            }
            #pragma unroll
            for (int jp = 0; jp < 4; jp++) {
                const int p   = lane >> 3;
                const int r   = t4*16 + ((p & 1) ? 8 : 0) + (lane & 7);
                const int col = jp*16 + ((p >= 2) ? 8 : 0);
                uint32_t th[4];
                ldsm4_t(th, v_u + 2*(r*APAD + col));
                #pragma unroll
                for (int mi = 0; mi < 2; mi++) {
                    mma16816(oacc[mi][2*jp],   pa[mi], th);
                    mma16816(oacc[mi][2*jp+1], pa[mi], th+2);
                }
            }
        }

        if (pf) CPA_WAIT0();
        __syncthreads();
    }

    // ---- epilogue: att = oacc / l -> single fp16 concat [b,s,h*64+dk] ----
    #pragma unroll
    for (int mi = 0; mi < 2; mi++) {
        const int qa = (mi == 0) ? qra0 : qra1;
        const float inv0 = 1.0f / lr[mi][0];
        const float inv1 = 1.0f / lr[mi][1];
        const size_t basea = ((size_t)(b*S_ + qa))*D_ + h*DK_;
        const size_t baseb = ((size_t)(b*S_ + qa + 8))*D_ + h*DK_;
        #pragma unroll
        for (int nj = 0; nj < 8; nj++) {
            const int dk = nj*8 + cc*2;
            *(uint32_t*)&g_att[basea + dk] = packh(oacc[mi][nj][0]*inv0, oacc[mi][nj][1]*inv0);
            *(uint32_t*)&g_att[baseb + dk] = packh(oacc[mi][nj][2]*inv1, oacc[mi][nj][3]*inv1);
        }
    }
}

// ---------------------------------------------------------------------------
extern "C" void kernel_launch(void* const* d_in, const int* in_sizes, int n_in,
                              void* d_out, int out_size)
{
    const float* q    = (const float*)d_in[0];
    const float* k    = (const float*)d_in[1];
    const float* v    = (const float*)d_in[2];
    const int*   mask = (const int*)  d_in[3];
    const float* Wq   = (const float*)d_in[4];
    const float* bq   = (const float*)d_in[5];
    const float* Wk   = (const float*)d_in[6];
    const float* bk   = (const float*)d_in[7];
    const float* Wv   = (const float*)d_in[8];
    const float* bv   = (const float*)d_in[9];
    const float* Wo   = (const float*)d_in[10];
    const float* bo   = (const float*)d_in[11];
    float* out = (float*)d_out;

    static int configured = 0;
    if (!configured) {
        cudaFuncSetAttribute(qkv_mma_kernel, cudaFuncAttributeMaxDynamicSharedMemorySize, PROJ_SMEM3);
        cudaFuncSetAttribute(out_mma_kernel, cudaFuncAttributeMaxDynamicSharedMemorySize, PROJ_SMEM1);
        cudaFuncSetAttribute(attn_mma_kernel, cudaFuncAttributeMaxDynamicSharedMemorySize, ATT_SMEM);
        configured = 1;
    }

    // 1. QKV projections: Q,K 3-term (exact score path); V 1-term
    qkv_mma_kernel<<<dim3(D_/256, M_/128, 3), 512, PROJ_SMEM3>>>(
        q, k, v, Wq, bq, Wk, bk, Wv, bv);

    // 2. Attention: QK 3-term, PV 1-term
    attn_mma_kernel<<<dim3(S_/256, B_*H_), 256, ATT_SMEM>>>(mask);

    // 3. Output projection: 1-term
    out_mma_kernel<<<dim3(D_/256, M_/128), 512, PROJ_SMEM1>>>(Wo, bo, out);
}

// round 14
// speedup vs baseline: 1.0355x; 1.0355x over previous
#include <cuda_runtime.h>
#include <cuda_fp16.h>
#include <cstdint>
#include <math.h>

#define B_ 2
#define S_ 2048
#define D_ 1024
#define H_ 16
#define DK_ 64
#define M_ (B_*S_)
#define NEGINF (-1000000000.0f)

// ---------------------------------------------------------------------------
// Scratch: 48 MiB. Score path (Q, K) hi/lo fp16; value path (V, att) single.
// ---------------------------------------------------------------------------
__device__ __half g_Qh_hi[M_*D_], g_Qh_lo[M_*D_];   // [bh][s][dk]
__device__ __half g_Kh_hi[M_*D_], g_Kh_lo[M_*D_];
__device__ __half g_Vh[M_*D_];
__device__ __half g_att[M_*D_];                     // [m][d] single fp16

// ---------------------------------------------------------------------------
// PTX helpers
// ---------------------------------------------------------------------------
__device__ __forceinline__ uint32_t smem_u32(const void* p) {
    uint32_t a;
    asm("{ .reg .u64 t; cvta.to.shared.u64 t, %1; cvt.u32.u64 %0, t; }" : "=r"(a) : "l"(p));
    return a;
}
__device__ __forceinline__ void ldsm4(uint32_t* r, uint32_t addr) {
    asm volatile("ldmatrix.sync.aligned.m8n8.x4.shared.b16 {%0,%1,%2,%3}, [%4];"
        : "=r"(r[0]), "=r"(r[1]), "=r"(r[2]), "=r"(r[3]) : "r"(addr));
}
__device__ __forceinline__ void ldsm4_t(uint32_t* r, uint32_t addr) {
    asm volatile("ldmatrix.sync.aligned.m8n8.x4.trans.shared.b16 {%0,%1,%2,%3}, [%4];"
        : "=r"(r[0]), "=r"(r[1]), "=r"(r[2]), "=r"(r[3]) : "r"(addr));
}
__device__ __forceinline__ void mma16816(float* d, const uint32_t* a, const uint32_t* b) {
    asm volatile(
        "mma.sync.aligned.m16n8k16.row.col.f32.f16.f16.f32 "
        "{%0,%1,%2,%3}, {%4,%5,%6,%7}, {%8,%9}, {%0,%1,%2,%3};"
        : "+f"(d[0]), "+f"(d[1]), "+f"(d[2]), "+f"(d[3])
        : "r"(a[0]), "r"(a[1]), "r"(a[2]), "r"(a[3]), "r"(b[0]), "r"(b[1]));
}
__device__ __forceinline__ void cpa16(uint32_t s, const void* g) {
    asm volatile("cp.async.cg.shared.global [%0], [%1], 16;" :: "r"(s), "l"(g));
}
#define CPA_COMMIT() asm volatile("cp.async.commit_group;" ::: "memory")
#define CPA_WAIT0()  asm volatile("cp.async.wait_group 0;" ::: "memory")

__device__ __forceinline__ uint32_t packh(float lo, float hi) {
    __half2 h = __floats2half2_rn(lo, hi);
    return *(uint32_t*)&h;
}
__device__ __forceinline__ float hres(float x) {
    return x - __half2float(__float2half_rn(x));
}
__device__ __forceinline__ void splith4(float4 x, uint2& h, uint2& l) {
    h.x = packh(x.x, x.y);  h.y = packh(x.z, x.w);
    l.x = packh(hres(x.x), hres(x.y));
    l.y = packh(hres(x.z), hres(x.w));
}
__device__ __forceinline__ uint2 cvt4(float4 x) {
    uint2 r; r.x = packh(x.x, x.y); r.y = packh(x.z, x.w); return r;
}
__device__ __forceinline__ void sts_split4(__half* hi, __half* lo,
                                           int row, int v, int pad, float4 x) {
    uint2 h, l; splith4(x, h, l);
    *(uint2*)(hi + row*pad + v*4) = h;
    *(uint2*)(lo + row*pad + v*4) = l;
}
__device__ __forceinline__ void sts_cvt4(__half* dst, int row, int v, int pad, float4 x) {
    *(uint2*)(dst + row*pad + v*4) = cvt4(x);
}

// ---------------------------------------------------------------------------
// Projection GEMM: C[m,n] = sum_k A[m,k]*W[n,k] + bias[n]
// 128x256 block, BK=64, 512 threads (16 warps 4m x 4n, warp tile 32x64).
// TERMS=3: A hi/lo x W hi/lo, 3 MMAs (Q-proj, exact score path).
// TERMS=2: A hi/lo x W single, 2 MMAs (K-proj).
// TERMS=1: A single x W single, 1 MMA (V-proj, out-proj).
// AHALF=1: A is fp16 single in gmem via cp.async (out-proj).
// MODE: 0 fp32 row-major; 1 fp16 hi/lo remap [bh,s,dk]; 2 fp16 single remap.
// ---------------------------------------------------------------------------
#define PPAD 72
#define PASLAB (128*PPAD)               // 9216
#define PWSLAB (256*PPAD)               // 18432
#define PROJ_SMEM3 (2*(2*PASLAB + 2*PWSLAB)*2)   // 221184 B (qkv launch: max stage)
#define PROJ_SMEM1 (2*(PASLAB + PWSLAB)*2)       // 110592 B (out-proj)

template<int TERMS>
__device__ __forceinline__ void proj_mma_kk(uint32_t stage_u, int kk, int wm, int wn,
                                            int lane, float acc[2][8][4])
{
    constexpr int ASL   = (TERMS >= 2) ? 2 : 1;
    constexpr int POFFW = ASL*PASLAB;
    uint32_t ah[2][4], al[2][4];
    #pragma unroll
    for (int mi = 0; mi < 2; mi++) {
        const int r   = wm*32 + mi*16 + (lane & 15);
        const int col = kk*16 + ((lane & 16) ? 8 : 0);
        ldsm4(ah[mi], stage_u + 2*(0*PASLAB + r*PPAD + col));
        if (TERMS >= 2) ldsm4(al[mi], stage_u + 2*(1*PASLAB + r*PPAD + col));
    }
    #pragma unroll
    for (int jp = 0; jp < 4; jp++) {
        const int p   = lane >> 3;
        const int r   = wn*64 + jp*16 + ((p >= 2) ? 8 : 0) + (lane & 7);
        const int col = kk*16 + ((p & 1) ? 8 : 0);
        uint32_t th[4], tl[4];
        ldsm4(th, stage_u + 2*(POFFW + r*PPAD + col));
        if (TERMS == 3) ldsm4(tl, stage_u + 2*(POFFW + PWSLAB + r*PPAD + col));
        #pragma unroll
        for (int mi = 0; mi < 2; mi++) {
            mma16816(acc[mi][2*jp], ah[mi], th);
            if (TERMS >= 2) mma16816(acc[mi][2*jp], al[mi], th);
            if (TERMS == 3) mma16816(acc[mi][2*jp], ah[mi], tl);
            mma16816(acc[mi][2*jp+1], ah[mi], th+2);
            if (TERMS >= 2) mma16816(acc[mi][2*jp+1], al[mi], th+2);
            if (TERMS == 3) mma16816(acc[mi][2*jp+1], ah[mi], tl+2);
        }
    }
}

template<int MODE, int TERMS, int AHALF>
__device__ __forceinline__ void proj_gemm(const float* __restrict__ Af,
                                          const __half* __restrict__ Ah16,
                                          const float* __restrict__ W,
                                          const float* __restrict__ bias,
                                          float* __restrict__ Cf,
                                          __half* __restrict__ Chi,
                                          __half* __restrict__ Clo)
{
    constexpr int ASL   = (TERMS >= 2) ? 2 : 1;
    constexpr int WSL   = (TERMS == 3) ? 2 : 1;
    constexpr int POFFW = ASL*PASLAB;
    constexpr int PSTG  = ASL*PASLAB + WSL*PWSLAB;

    extern __shared__ __half sm[];
    const uint32_t sb = smem_u32(sm);
    const int tid  = threadIdx.x;
    const int lane = tid & 31;
    const int wid  = tid >> 5;
    const int wm   = wid & 3;
    const int wn   = wid >> 2;
    const int m0 = blockIdx.y * 128;
    const int n0 = blockIdx.x * 256;

    const int frow = tid >> 4;            // 0..31 (+it*32); fp32 float4 loads
    const int fv   = tid & 15;

    float acc[2][8][4];
    #pragma unroll
    for (int mi = 0; mi < 2; mi++)
        #pragma unroll
        for (int nj = 0; nj < 8; nj++)
            #pragma unroll
            for (int e = 0; e < 4; e++) acc[mi][nj][e] = 0.0f;

    float4 pa[4], pw[4];

    // ---- prologue: chunk 0 -> stage 0 ----
    if (AHALF) {
        #pragma unroll
        for (int it = 0; it < 2; it++) {
            const int idx = tid + it*512;          // 0..1023
            const int row = idx >> 3, v = idx & 7;
            cpa16(sb + 2*(row*PPAD + v*8), Ah16 + (size_t)(m0+row)*D_ + v*8);
        }
        CPA_COMMIT();
    } else {
        #pragma unroll
        for (int it = 0; it < 4; it++) {
            const int row = frow + it*32;
            float4 x = *((const float4*)(Af + (size_t)(m0+row)*D_) + fv);
            if (TERMS >= 2) sts_split4(sm, sm + PASLAB, row, fv, PPAD, x);
            else            sts_cvt4(sm, row, fv, PPAD, x);
        }
    }
    #pragma unroll
    for (int it = 0; it < 8; it++) {
        const int row = frow + it*32;
        float4 x = *((const float4*)(W + (size_t)(n0+row)*D_) + fv);
        if (TERMS == 3) sts_split4(sm + POFFW, sm + POFFW + PWSLAB, row, fv, PPAD, x);
        else            sts_cvt4(sm + POFFW, row, fv, PPAD, x);
    }
    if (AHALF) CPA_WAIT0();
    __syncthreads();

    for (int c = 0; c < 16; c++) {
        const int cur = c & 1;
        const int nxt = cur ^ 1;
        const uint32_t scur_u = sb + 2*(cur*PSTG);
        const uint32_t snx_u  = sb + 2*(nxt*PSTG);
        __half* snx = sm + nxt*PSTG;
        const int k1 = (c + 1) * 64;
        const bool pf = (c < 15);

        if (pf) {
            if (AHALF) {
                #pragma unroll
                for (int it = 0; it < 2; it++) {
                    const int idx = tid + it*512;
                    const int row = idx >> 3, v = idx & 7;
                    cpa16(snx_u + 2*(row*PPAD + v*8),
                          Ah16 + (size_t)(m0+row)*D_ + k1 + v*8);
                }
                CPA_COMMIT();
            } else {
                #pragma unroll
                for (int it = 0; it < 4; it++) {
                    const int row = frow + it*32;
                    pa[it] = *((const float4*)(Af + (size_t)(m0+row)*D_ + k1) + fv);
                }
            }
        }
        proj_mma_kk<TERMS>(scur_u, 0, wm, wn, lane, acc);
        if (pf) {
            if (!AHALF) {
                #pragma unroll
                for (int it = 0; it < 4; it++) {
                    if (TERMS >= 2) sts_split4(snx, snx + PASLAB, frow + it*32, fv, PPAD, pa[it]);
                    else            sts_cvt4(snx, frow + it*32, fv, PPAD, pa[it]);
                }
            }
            #pragma unroll
            for (int it = 0; it < 4; it++) {
                const int row = frow + it*32;
                pw[it] = *((const float4*)(W + (size_t)(n0+row)*D_ + k1) + fv);
            }
        }
        proj_mma_kk<TERMS>(scur_u, 1, wm, wn, lane, acc);
        if (pf) {
            #pragma unroll
            for (int it = 0; it < 4; it++) {
                if (TERMS == 3) sts_split4(snx + POFFW, snx + POFFW + PWSLAB,
                                           frow + it*32, fv, PPAD, pw[it]);
                else            sts_cvt4(snx + POFFW, frow + it*32, fv, PPAD, pw[it]);
            }
            #pragma unroll
            for (int it = 0; it < 4; it++) {
                const int row = frow + (it + 4)*32;
                pw[it] = *((const float4*)(W + (size_t)(n0+row)*D_ + k1) + fv);
            }
        }
        proj_mma_kk<TERMS>(scur_u, 2, wm, wn, lane, acc);
        if (pf) {
            #pragma unroll
            for (int it = 0; it < 4; it++) {
                if (TERMS == 3) sts_split4(snx + POFFW, snx + POFFW + PWSLAB,
                                           frow + (it + 4)*32, fv, PPAD, pw[it]);
                else            sts_cvt4(snx + POFFW, frow + (it + 4)*32, fv, PPAD, pw[it]);
            }
        }
        proj_mma_kk<TERMS>(scur_u, 3, wm, wn, lane, acc);
        if (pf && AHALF) CPA_WAIT0();
        __syncthreads();
    }

    // ---- epilogue ----
    const int g  = lane >> 2;
    const int cc = lane & 3;
    #pragma unroll
    for (int mi = 0; mi < 2; mi++) {
        const int ra = m0 + wm*32 + mi*16 + g;
        const int rb = ra + 8;
        #pragma unroll
        for (int nj = 0; nj < 8; nj++) {
            const int col = n0 + wn*64 + nj*8 + cc*2;
            const float b0 = bias[col], b1 = bias[col+1];
            const float v00 = acc[mi][nj][0] + b0, v01 = acc[mi][nj][1] + b1;
            const float v10 = acc[mi][nj][2] + b0, v11 = acc[mi][nj][3] + b1;
            if (MODE == 0) {
                *(float2*)&Cf[(size_t)ra*D_ + col] = make_float2(v00, v01);
                *(float2*)&Cf[(size_t)rb*D_ + col] = make_float2(v10, v11);
            } else {
                const int h = col >> 6, dk = col & 63;
                const int ba = ra >> 11, sa = ra & (S_-1);
                const int bb = rb >> 11, sb2 = rb & (S_-1);
                const size_t ia = (((size_t)ba*H_ + h)*S_ + sa)*DK_ + dk;
                const size_t ib = (((size_t)bb*H_ + h)*S_ + sb2)*DK_ + dk;
                *(uint32_t*)&Chi[ia] = packh(v00, v01);
                *(uint32_t*)&Chi[ib] = packh(v10, v11);
                if (MODE == 1) {
                    *(uint32_t*)&Clo[ia] = packh(hres(v00), hres(v01));
                    *(uint32_t*)&Clo[ib] = packh(hres(v10), hres(v11));
                }
            }
        }
    }
}

__global__ void __launch_bounds__(512, 1)
qkv_mma_kernel(const float* __restrict__ q, const float* __restrict__ k,
               const float* __restrict__ v,
               const float* __restrict__ Wq, const float* __restrict__ bq,
               const float* __restrict__ Wk, const float* __restrict__ bk,
               const float* __restrict__ Wv, const float* __restrict__ bv)
{
    const int z = blockIdx.z;
    if (z == 0)      proj_gemm<1,3,0>(q, nullptr, Wq, bq, nullptr, g_Qh_hi, g_Qh_lo);
    else if (z == 1) proj_gemm<1,2,0>(k, nullptr, Wk, bk, nullptr, g_Kh_hi, g_Kh_lo);
    else             proj_gemm<2,1,0>(v, nullptr, Wv, bv, nullptr, g_Vh, nullptr);
}

__global__ void __launch_bounds__(512, 1)
out_mma_kernel(const float* __restrict__ Wo, const float* __restrict__ bo,
               float* __restrict__ out)
{
    proj_gemm<0,1,1>(nullptr, g_att, Wo, bo, out, nullptr, nullptr);
}

// ---------------------------------------------------------------------------
// Flash attention. QK 3-term (Q hi/lo x K hi/lo); PV 1-term.
// 128 threads (4 warps x m32 = 128 q rows/CTA), 2 CTAs/SM for MMA/softmax
// overlap. K hi/lo + V single double-buffered via cp.async. Mask: query rows.
// ---------------------------------------------------------------------------
#define APAD 72
#define AQSLAB (128*APAD)                  // 9216 elems per Q slab
#define ASLAB  (64*APAD)                   // 4608 elems per KV slab
#define AKV0   (2*AQSLAB)
// KV slabs: [K0h K0l K1h K1l V0 V1]
#define ATT_SMEM ((2*AQSLAB + 6*ASLAB)*2)  // 92160 B -> 2 CTAs/SM

__global__ void __launch_bounds__(128, 2)
attn_mma_kernel(const int* __restrict__ mask)
{
    extern __shared__ __half sm[];
    const uint32_t sb = smem_u32(sm);
    const int tid  = threadIdx.x;
    const int lane = tid & 31;
    const int wid  = tid >> 5;             // 0..3
    const int g    = lane >> 2;
    const int cc   = lane & 3;

    const int bh = blockIdx.y;
    const int b  = bh >> 4;
    const int h  = bh & 15;
    const int q0 = blockIdx.x * 128;

    const __half* Qhi = g_Qh_hi + (size_t)bh*S_*DK_;
    const __half* Qlo = g_Qh_lo + (size_t)bh*S_*DK_;
    const __half* Khi = g_Kh_hi + (size_t)bh*S_*DK_;
    const __half* Klo = g_Kh_lo + (size_t)bh*S_*DK_;
    const __half* Vp  = g_Vh + (size_t)bh*S_*DK_;
    const int* mp = mask + b*S_;

    // ---- issue KV tile 0 via cp.async; load Q concurrently ----
    {
        #pragma unroll
        for (int i = 0; i < 4; i++) {
            const int idx = tid + i*128;           // 0..511
            const int row = idx >> 3, v = idx & 7;
            const uint32_t so = sb + 2*(AKV0 + row*APAD + v*8);
            const size_t  go = (size_t)row*DK_ + v*8;
            cpa16(so + 2*(0*ASLAB), Khi + go);
            cpa16(so + 2*(1*ASLAB), Klo + go);
            cpa16(so + 2*(4*ASLAB), Vp + go);
        }
        CPA_COMMIT();
    }
    #pragma unroll
    for (int it = 0; it < 8; it++) {
        const int idx = tid + it*128;              // 0..1023
        const int row = idx >> 3, v = idx & 7;
        *(uint4*)(sm + 0      + row*APAD + v*8) =
            *((const uint4*)(Qhi + (size_t)(q0+row)*DK_) + v);
        *(uint4*)(sm + AQSLAB + row*APAD + v*8) =
            *((const uint4*)(Qlo + (size_t)(q0+row)*DK_) + v);
    }
    CPA_WAIT0();
    __syncthreads();

    const int qra0 = q0 + wid*32 + g;
    const int qra1 = qra0 + 16;
    bool msk[2][2];
    msk[0][0] = (mp[qra0] == 0);      msk[0][1] = (mp[qra0 + 8] == 0);
    msk[1][0] = (mp[qra1] == 0);      msk[1][1] = (mp[qra1 + 8] == 0);

    float mr[2][2], lr[2][2];
    #pragma unroll
    for (int mi = 0; mi < 2; mi++) { mr[mi][0] = mr[mi][1] = -1e30f; lr[mi][0] = lr[mi][1] = 0.0f; }

    float oacc[2][8][4];
    #pragma unroll
    for (int mi = 0; mi < 2; mi++)
        #pragma unroll
        for (int nj = 0; nj < 8; nj++)
            #pragma unroll
            for (int e = 0; e < 4; e++) oacc[mi][nj][e] = 0.0f;

    for (int t = 0; t < 32; t++) {
        const int cur = t & 1;
        const int nxt = cur ^ 1;
        const bool pf = (t + 1 < 32);
        const uint32_t kh_u = sb + 2*(AKV0 + (2*cur)*ASLAB);
        const uint32_t kl_u = kh_u + 2*ASLAB;
        const uint32_t v_u  = sb + 2*(AKV0 + (4 + cur)*ASLAB);

        if (pf) {
            const size_t base = (size_t)((t + 1)*64)*DK_;
            #pragma unroll
            for (int i = 0; i < 4; i++) {
                const int idx = tid + i*128;
                const int row = idx >> 3, v = idx & 7;
                const uint32_t so = sb + 2*(AKV0 + row*APAD + v*8);
                const size_t  go = base + (size_t)row*DK_ + v*8;
                cpa16(so + 2*((2*nxt)*ASLAB),   Khi + go);
                cpa16(so + 2*((2*nxt+1)*ASLAB), Klo + go);
                cpa16(so + 2*((4 + nxt)*ASLAB), Vp + go);
            }
            CPA_COMMIT();
        }

        // ---- S = Q K^T (3-term exact score path) ----
        float sacc[2][8][4];
        #pragma unroll
        for (int mi = 0; mi < 2; mi++)
            #pragma unroll
            for (int nj = 0; nj < 8; nj++)
                #pragma unroll
                for (int e = 0; e < 4; e++) sacc[mi][nj][e] = 0.0f;

        #pragma unroll
        for (int kk = 0; kk < 4; kk++) {
            uint32_t aqh[2][4], aql[2][4];
            #pragma unroll
            for (int mi = 0; mi < 2; mi++) {
                const int r   = wid*32 + mi*16 + (lane & 15);
                const int col = kk*16 + ((lane & 16) ? 8 : 0);
                ldsm4(aqh[mi], sb + 2*(0      + r*APAD + col));
                ldsm4(aql[mi], sb + 2*(AQSLAB + r*APAD + col));
            }
            #pragma unroll
            for (int jp = 0; jp < 4; jp++) {
                const int p   = lane >> 3;
                const int r   = jp*16 + ((p >= 2) ? 8 : 0) + (lane & 7);
                const int col = kk*16 + ((p & 1) ? 8 : 0);
                uint32_t th[4], tl[4];
                ldsm4(th, kh_u + 2*(r*APAD + col));
                ldsm4(tl, kl_u + 2*(r*APAD + col));
                #pragma unroll
                for (int mi = 0; mi < 2; mi++) {
                    mma16816(sacc[mi][2*jp],   aqh[mi], th);
                    mma16816(sacc[mi][2*jp],   aql[mi], th);
                    mma16816(sacc[mi][2*jp],   aqh[mi], tl);
                    mma16816(sacc[mi][2*jp+1], aqh[mi], th+2);
                    mma16816(sacc[mi][2*jp+1], aql[mi], th+2);
                    mma16816(sacc[mi][2*jp+1], aqh[mi], tl+2);
                }
            }
        }

        // ---- mask + online softmax ----
        #pragma unroll
        for (int mi = 0; mi < 2; mi++) {
            if (msk[mi][0]) {
                #pragma unroll
                for (int nj = 0; nj < 8; nj++) { sacc[mi][nj][0] = NEGINF; sacc[mi][nj][1] = NEGINF; }
            }
            if (msk[mi][1]) {
                #pragma unroll
                for (int nj = 0; nj < 8; nj++) { sacc[mi][nj][2] = NEGINF; sacc[mi][nj][3] = NEGINF; }
            }

            float mx0 = -1e30f, mx1 = -1e30f;
            #pragma unroll
            for (int nj = 0; nj < 8; nj++) {
                mx0 = fmaxf(mx0, fmaxf(sacc[mi][nj][0], sacc[mi][nj][1]));
                mx1 = fmaxf(mx1, fmaxf(sacc[mi][nj][2], sacc[mi][nj][3]));
            }
            mx0 = fmaxf(mx0, __shfl_xor_sync(0xffffffffu, mx0, 1));
            mx0 = fmaxf(mx0, __shfl_xor_sync(0xffffffffu, mx0, 2));
            mx1 = fmaxf(mx1, __shfl_xor_sync(0xffffffffu, mx1, 1));
            mx1 = fmaxf(mx1, __shfl_xor_sync(0xffffffffu, mx1, 2));

            const float mn0 = fmaxf(mr[mi][0], mx0);
            const float mn1 = fmaxf(mr[mi][1], mx1);
            const float al0 = __expf(mr[mi][0] - mn0);
            const float al1 = __expf(mr[mi][1] - mn1);
            mr[mi][0] = mn0; mr[mi][1] = mn1;

            float rs0 = 0.0f, rs1 = 0.0f;
            #pragma unroll
            for (int nj = 0; nj < 8; nj++) {
                const float p0 = __expf(sacc[mi][nj][0] - mn0);
                const float p1 = __expf(sacc[mi][nj][1] - mn0);
                const float p2 = __expf(sacc[mi][nj][2] - mn1);
                const float p3 = __expf(sacc[mi][nj][3] - mn1);
                sacc[mi][nj][0] = p0; sacc[mi][nj][1] = p1;
                sacc[mi][nj][2] = p2; sacc[mi][nj][3] = p3;
                rs0 += p0 + p1; rs1 += p2 + p3;
            }
            rs0 += __shfl_xor_sync(0xffffffffu, rs0, 1);
            rs0 += __shfl_xor_sync(0xffffffffu, rs0, 2);
            rs1 += __shfl_xor_sync(0xffffffffu, rs1, 1);
            rs1 += __shfl_xor_sync(0xffffffffu, rs1, 2);
            lr[mi][0] = lr[mi][0]*al0 + rs0;
            lr[mi][1] = lr[mi][1]*al1 + rs1;

            #pragma unroll
            for (int nj = 0; nj < 8; nj++) {
                oacc[mi][nj][0] *= al0; oacc[mi][nj][1] *= al0;
                oacc[mi][nj][2] *= al1; oacc[mi][nj][3] *= al1;
            }
        }

        // ---- O += P V (1-term) ----
        #pragma unroll
        for (int t4 = 0; t4 < 4; t4++) {
            uint32_t pa[2][4];
            #pragma unroll
            for (int mi = 0; mi < 2; mi++) {
                pa[mi][0] = packh(sacc[mi][2*t4][0],   sacc[mi][2*t4][1]);
                pa[mi][1] = packh(sacc[mi][2*t4][2],   sacc[mi][2*t4][3]);
                pa[mi][2] = packh(sacc[mi][2*t4+1][0], sacc[mi][2*t4+1][1]);
                pa[mi][3] = packh(sacc[mi][2*t4+1][2], sacc[mi][2*t4+1][3]);
            }
            #pragma unroll
            for (int jp = 0; jp < 4; jp++) {
                const int p   = lane >> 3;
                const int r   = t4*16 + ((p & 1) ? 8 : 0) + (lane & 7);
                const int col = jp*16 + ((p >= 2) ? 8 : 0);
                uint32_t th[4];
                ldsm4_t(th, v_u + 2*(r*APAD + col));
                #pragma unroll
                for (int mi = 0; mi < 2; mi++) {
                    mma16816(oacc[mi][2*jp],   pa[mi], th);
                    mma16816(oacc[mi][2*jp+1], pa[mi], th+2);
                }
            }
        }

        if (pf) CPA_WAIT0();
        __syncthreads();
    }

    // ---- epilogue: att = oacc / l -> single fp16 concat [b,s,h*64+dk] ----
    #pragma unroll
    for (int mi = 0; mi < 2; mi++) {
        const int qa = (mi == 0) ? qra0 : qra1;
        const float inv0 = 1.0f / lr[mi][0];
        const float inv1 = 1.0f / lr[mi][1];
        const size_t basea = ((size_t)(b*S_ + qa))*D_ + h*DK_;
        const size_t baseb = ((size_t)(b*S_ + qa + 8))*D_ + h*DK_;
        #pragma unroll
        for (int nj = 0; nj < 8; nj++) {
            const int dk = nj*8 + cc*2;
            *(uint32_t*)&g_att[basea + dk] = packh(oacc[mi][nj][0]*inv0, oacc[mi][nj][1]*inv0);
            *(uint32_t*)&g_att[baseb + dk] = packh(oacc[mi][nj][2]*inv1, oacc[mi][nj][3]*inv1);
        }
    }
}

// ---------------------------------------------------------------------------
extern "C" void kernel_launch(void* const* d_in, const int* in_sizes, int n_in,
                              void* d_out, int out_size)
{
    const float* q    = (const float*)d_in[0];
    const float* k    = (const float*)d_in[1];
    const float* v    = (const float*)d_in[2];
    const int*   mask = (const int*)  d_in[3];
    const float* Wq   = (const float*)d_in[4];
    const float* bq   = (const float*)d_in[5];
    const float* Wk   = (const float*)d_in[6];
    const float* bk   = (const float*)d_in[7];
    const float* Wv   = (const float*)d_in[8];
    const float* bv   = (const float*)d_in[9];
    const float* Wo   = (const float*)d_in[10];
    const float* bo   = (const float*)d_in[11];
    float* out = (float*)d_out;

    static int configured = 0;
    if (!configured) {
        cudaFuncSetAttribute(qkv_mma_kernel, cudaFuncAttributeMaxDynamicSharedMemorySize, PROJ_SMEM3);
        cudaFuncSetAttribute(out_mma_kernel, cudaFuncAttributeMaxDynamicSharedMemorySize, PROJ_SMEM1);
        cudaFuncSetAttribute(attn_mma_kernel, cudaFuncAttributeMaxDynamicSharedMemorySize, ATT_SMEM);
        configured = 1;
    }

    // 1. QKV projections: Q 3-term, K 2-term, V 1-term
    qkv_mma_kernel<<<dim3(D_/256, M_/128, 3), 512, PROJ_SMEM3>>>(
        q, k, v, Wq, bq, Wk, bk, Wv, bv);

    // 2. Attention: QK 3-term, PV 1-term; 4-warp CTAs, 2 CTAs/SM
    attn_mma_kernel<<<dim3(S_/128, B_*H_), 128, ATT_SMEM>>>(mask);

    // 3. Output projection: 1-term
    out_mma_kernel<<<dim3(D_/256, M_/128), 512, PROJ_SMEM1>>>(Wo, bo, out);
}

// round 16
// speedup vs baseline: 1.1585x; 1.1187x over previous
#include <cuda_runtime.h>
#include <cuda_fp16.h>
#include <cstdint>
#include <math.h>

#define B_ 2
#define S_ 2048
#define D_ 1024
#define H_ 16
#define DK_ 64
#define M_ (B_*S_)
#define NEGINF (-1000000000.0f)

// ---------------------------------------------------------------------------
// Scratch: 40 MiB. Q hi/lo fp16 (exact score-side operand);
// K, V, att single fp16.
// ---------------------------------------------------------------------------
__device__ __half g_Qh_hi[M_*D_], g_Qh_lo[M_*D_];   // [bh][s][dk]
__device__ __half g_Kh[M_*D_];                      // single fp16
__device__ __half g_Vh[M_*D_];
__device__ __half g_att[M_*D_];                     // [m][d]

// ---------------------------------------------------------------------------
// PTX helpers
// ---------------------------------------------------------------------------
__device__ __forceinline__ uint32_t smem_u32(const void* p) {
    uint32_t a;
    asm("{ .reg .u64 t; cvta.to.shared.u64 t, %1; cvt.u32.u64 %0, t; }" : "=r"(a) : "l"(p));
    return a;
}
__device__ __forceinline__ void ldsm4(uint32_t* r, uint32_t addr) {
    asm volatile("ldmatrix.sync.aligned.m8n8.x4.shared.b16 {%0,%1,%2,%3}, [%4];"
        : "=r"(r[0]), "=r"(r[1]), "=r"(r[2]), "=r"(r[3]) : "r"(addr));
}
__device__ __forceinline__ void ldsm4_t(uint32_t* r, uint32_t addr) {
    asm volatile("ldmatrix.sync.aligned.m8n8.x4.trans.shared.b16 {%0,%1,%2,%3}, [%4];"
        : "=r"(r[0]), "=r"(r[1]), "=r"(r[2]), "=r"(r[3]) : "r"(addr));
}
__device__ __forceinline__ void mma16816(float* d, const uint32_t* a, const uint32_t* b) {
    asm volatile(
        "mma.sync.aligned.m16n8k16.row.col.f32.f16.f16.f32 "
        "{%0,%1,%2,%3}, {%4,%5,%6,%7}, {%8,%9}, {%0,%1,%2,%3};"
        : "+f"(d[0]), "+f"(d[1]), "+f"(d[2]), "+f"(d[3])
        : "r"(a[0]), "r"(a[1]), "r"(a[2]), "r"(a[3]), "r"(b[0]), "r"(b[1]));
}
__device__ __forceinline__ void cpa16(uint32_t s, const void* g) {
    asm volatile("cp.async.cg.shared.global [%0], [%1], 16;" :: "r"(s), "l"(g));
}
#define CPA_COMMIT() asm volatile("cp.async.commit_group;" ::: "memory")
#define CPA_WAIT0()  asm volatile("cp.async.wait_group 0;" ::: "memory")

__device__ __forceinline__ uint32_t packh(float lo, float hi) {
    __half2 h = __floats2half2_rn(lo, hi);
    return *(uint32_t*)&h;
}
__device__ __forceinline__ float hres(float x) {
    return x - __half2float(__float2half_rn(x));
}
__device__ __forceinline__ void splith4(float4 x, uint2& h, uint2& l) {
    h.x = packh(x.x, x.y);  h.y = packh(x.z, x.w);
    l.x = packh(hres(x.x), hres(x.y));
    l.y = packh(hres(x.z), hres(x.w));
}
__device__ __forceinline__ uint2 cvt4(float4 x) {
    uint2 r; r.x = packh(x.x, x.y); r.y = packh(x.z, x.w); return r;
}
__device__ __forceinline__ void sts_split4(__half* hi, __half* lo,
                                           int row, int v, int pad, float4 x) {
    uint2 h, l; splith4(x, h, l);
    *(uint2*)(hi + row*pad + v*4) = h;
    *(uint2*)(lo + row*pad + v*4) = l;
}
__device__ __forceinline__ void sts_cvt4(__half* dst, int row, int v, int pad, float4 x) {
    *(uint2*)(dst + row*pad + v*4) = cvt4(x);
}

// ---------------------------------------------------------------------------
// Projection GEMM: C[m,n] = sum_k A[m,k]*W[n,k] + bias[n]
// 128x256 block, BK=64, 512 threads (16 warps 4m x 4n, warp tile 32x64).
// TERMS=3: A hi/lo x W hi/lo (Q-proj). TERMS=2: A hi/lo x W single (K-proj).
// TERMS=1: A single x W single (V-proj, out-proj).
// AHALF=1: A fp16 single via cp.async (out-proj).
// MODE: 0 fp32 row-major; 1 fp16 hi/lo remap [bh,s,dk]; 2 fp16 single remap.
// ---------------------------------------------------------------------------
#define PPAD 72
#define PASLAB (128*PPAD)               // 9216
#define PWSLAB (256*PPAD)               // 18432
#define PROJ_SMEM3 (2*(2*PASLAB + 2*PWSLAB)*2)   // 221184 B
#define PROJ_SMEM1 (2*(PASLAB + PWSLAB)*2)       // 110592 B

template<int TERMS>
__device__ __forceinline__ void proj_mma_kk(uint32_t stage_u, int kk, int wm, int wn,
                                            int lane, float acc[2][8][4])
{
    constexpr int ASL   = (TERMS >= 2) ? 2 : 1;
    constexpr int POFFW = ASL*PASLAB;
    uint32_t ah[2][4], al[2][4];
    #pragma unroll
    for (int mi = 0; mi < 2; mi++) {
        const int r   = wm*32 + mi*16 + (lane & 15);
        const int col = kk*16 + ((lane & 16) ? 8 : 0);
        ldsm4(ah[mi], stage_u + 2*(0*PASLAB + r*PPAD + col));
        if (TERMS >= 2) ldsm4(al[mi], stage_u + 2*(1*PASLAB + r*PPAD + col));
    }
    #pragma unroll
    for (int jp = 0; jp < 4; jp++) {
        const int p   = lane >> 3;
        const int r   = wn*64 + jp*16 + ((p >= 2) ? 8 : 0) + (lane & 7);
        const int col = kk*16 + ((p & 1) ? 8 : 0);
        uint32_t th[4], tl[4];
        ldsm4(th, stage_u + 2*(POFFW + r*PPAD + col));
        if (TERMS == 3) ldsm4(tl, stage_u + 2*(POFFW + PWSLAB + r*PPAD + col));
        #pragma unroll
        for (int mi = 0; mi < 2; mi++) {
            mma16816(acc[mi][2*jp], ah[mi], th);
            if (TERMS >= 2) mma16816(acc[mi][2*jp], al[mi], th);
            if (TERMS == 3) mma16816(acc[mi][2*jp], ah[mi], tl);
            mma16816(acc[mi][2*jp+1], ah[mi], th+2);
            if (TERMS >= 2) mma16816(acc[mi][2*jp+1], al[mi], th+2);
            if (TERMS == 3) mma16816(acc[mi][2*jp+1], ah[mi], tl+2);
        }
    }
}

template<int MODE, int TERMS, int AHALF>
__device__ __forceinline__ void proj_gemm(const float* __restrict__ Af,
                                          const __half* __restrict__ Ah16,
                                          const float* __restrict__ W,
                                          const float* __restrict__ bias,
                                          float* __restrict__ Cf,
                                          __half* __restrict__ Chi,
                                          __half* __restrict__ Clo)
{
    constexpr int ASL   = (TERMS >= 2) ? 2 : 1;
    constexpr int WSL   = (TERMS == 3) ? 2 : 1;
    constexpr int POFFW = ASL*PASLAB;
    constexpr int PSTG  = ASL*PASLAB + WSL*PWSLAB;

    extern __shared__ __half sm[];
    const uint32_t sb = smem_u32(sm);
    const int tid  = threadIdx.x;
    const int lane = tid & 31;
    const int wid  = tid >> 5;
    const int wm   = wid & 3;
    const int wn   = wid >> 2;
    const int m0 = blockIdx.y * 128;
    const int n0 = blockIdx.x * 256;

    const int frow = tid >> 4;            // 0..31 (+it*32); fp32 float4 loads
    const int fv   = tid & 15;

    float acc[2][8][4];
    #pragma unroll
    for (int mi = 0; mi < 2; mi++)
        #pragma unroll
        for (int nj = 0; nj < 8; nj++)
            #pragma unroll
            for (int e = 0; e < 4; e++) acc[mi][nj][e] = 0.0f;

    float4 pa[4], pw[4];

    // ---- prologue: chunk 0 -> stage 0 ----
    if (AHALF) {
        #pragma unroll
        for (int it = 0; it < 2; it++) {
            const int idx = tid + it*512;          // 0..1023
            const int row = idx >> 3, v = idx & 7;
            cpa16(sb + 2*(row*PPAD + v*8), Ah16 + (size_t)(m0+row)*D_ + v*8);
        }
        CPA_COMMIT();
    } else {
        #pragma unroll
        for (int it = 0; it < 4; it++) {
            const int row = frow + it*32;
            float4 x = *((const float4*)(Af + (size_t)(m0+row)*D_) + fv);
            if (TERMS >= 2) sts_split4(sm, sm + PASLAB, row, fv, PPAD, x);
            else            sts_cvt4(sm, row, fv, PPAD, x);
        }
    }
    #pragma unroll
    for (int it = 0; it < 8; it++) {
        const int row = frow + it*32;
        float4 x = *((const float4*)(W + (size_t)(n0+row)*D_) + fv);
        if (TERMS == 3) sts_split4(sm + POFFW, sm + POFFW + PWSLAB, row, fv, PPAD, x);
        else            sts_cvt4(sm + POFFW, row, fv, PPAD, x);
    }
    if (AHALF) CPA_WAIT0();
    __syncthreads();

    for (int c = 0; c < 16; c++) {
        const int cur = c & 1;
        const int nxt = cur ^ 1;
        const uint32_t scur_u = sb + 2*(cur*PSTG);
        const uint32_t snx_u  = sb + 2*(nxt*PSTG);
        __half* snx = sm + nxt*PSTG;
        const int k1 = (c + 1) * 64;
        const bool pf = (c < 15);

        if (pf) {
            if (AHALF) {
                #pragma unroll
                for (int it = 0; it < 2; it++) {
                    const int idx = tid + it*512;
                    const int row = idx >> 3, v = idx & 7;
                    cpa16(snx_u + 2*(row*PPAD + v*8),
                          Ah16 + (size_t)(m0+row)*D_ + k1 + v*8);
                }
                CPA_COMMIT();
            } else {
                #pragma unroll
                for (int it = 0; it < 4; it++) {
                    const int row = frow + it*32;
                    pa[it] = *((const float4*)(Af + (size_t)(m0+row)*D_ + k1) + fv);
                }
            }
        }
        proj_mma_kk<TERMS>(scur_u, 0, wm, wn, lane, acc);
        if (pf) {
            if (!AHALF) {
                #pragma unroll
                for (int it = 0; it < 4; it++) {
                    if (TERMS >= 2) sts_split4(snx, snx + PASLAB, frow + it*32, fv, PPAD, pa[it]);
                    else            sts_cvt4(snx, frow + it*32, fv, PPAD, pa[it]);
                }
            }
            #pragma unroll
            for (int it = 0; it < 4; it++) {
                const int row = frow + it*32;
                pw[it] = *((const float4*)(W + (size_t)(n0+row)*D_ + k1) + fv);
            }
        }
        proj_mma_kk<TERMS>(scur_u, 1, wm, wn, lane, acc);
        if (pf) {
            #pragma unroll
            for (int it = 0; it < 4; it++) {
                if (TERMS == 3) sts_split4(snx + POFFW, snx + POFFW + PWSLAB,
                                           frow + it*32, fv, PPAD, pw[it]);
                else            sts_cvt4(snx + POFFW, frow + it*32, fv, PPAD, pw[it]);
            }
            #pragma unroll
            for (int it = 0; it < 4; it++) {
                const int row = frow + (it + 4)*32;
                pw[it] = *((const float4*)(W + (size_t)(n0+row)*D_ + k1) + fv);
            }
        }
        proj_mma_kk<TERMS>(scur_u, 2, wm, wn, lane, acc);
        if (pf) {
            #pragma unroll
            for (int it = 0; it < 4; it++) {
                if (TERMS == 3) sts_split4(snx + POFFW, snx + POFFW + PWSLAB,
                                           frow + (it + 4)*32, fv, PPAD, pw[it]);
                else            sts_cvt4(snx + POFFW, frow + (it + 4)*32, fv, PPAD, pw[it]);
            }
        }
        proj_mma_kk<TERMS>(scur_u, 3, wm, wn, lane, acc);
        if (pf && AHALF) CPA_WAIT0();
        __syncthreads();
    }

    // ---- epilogue ----
    const int g  = lane >> 2;
    const int cc = lane & 3;
    #pragma unroll
    for (int mi = 0; mi < 2; mi++) {
        const int ra = m0 + wm*32 + mi*16 + g;
        const int rb = ra + 8;
        #pragma unroll
        for (int nj = 0; nj < 8; nj++) {
            const int col = n0 + wn*64 + nj*8 + cc*2;
            const float b0 = bias[col], b1 = bias[col+1];
            const float v00 = acc[mi][nj][0] + b0, v01 = acc[mi][nj][1] + b1;
            const float v10 = acc[mi][nj][2] + b0, v11 = acc[mi][nj][3] + b1;
            if (MODE == 0) {
                *(float2*)&Cf[(size_t)ra*D_ + col] = make_float2(v00, v01);
                *(float2*)&Cf[(size_t)rb*D_ + col] = make_float2(v10, v11);
            } else {
                const int h = col >> 6, dk = col & 63;
                const int ba = ra >> 11, sa = ra & (S_-1);
                const int bb = rb >> 11, sb2 = rb & (S_-1);
                const size_t ia = (((size_t)ba*H_ + h)*S_ + sa)*DK_ + dk;
                const size_t ib = (((size_t)bb*H_ + h)*S_ + sb2)*DK_ + dk;
                *(uint32_t*)&Chi[ia] = packh(v00, v01);
                *(uint32_t*)&Chi[ib] = packh(v10, v11);
                if (MODE == 1) {
                    *(uint32_t*)&Clo[ia] = packh(hres(v00), hres(v01));
                    *(uint32_t*)&Clo[ib] = packh(hres(v10), hres(v11));
                }
            }
        }
    }
}

__global__ void __launch_bounds__(512, 1)
qkv_mma_kernel(const float* __restrict__ q, const float* __restrict__ k,
               const float* __restrict__ v,
               const float* __restrict__ Wq, const float* __restrict__ bq,
               const float* __restrict__ Wk, const float* __restrict__ bk,
               const float* __restrict__ Wv, const float* __restrict__ bv)
{
    const int z = blockIdx.z;
    if (z == 0)      proj_gemm<1,3,0>(q, nullptr, Wq, bq, nullptr, g_Qh_hi, g_Qh_lo);
    else if (z == 1) proj_gemm<2,2,0>(k, nullptr, Wk, bk, nullptr, g_Kh, nullptr);
    else             proj_gemm<2,1,0>(v, nullptr, Wv, bv, nullptr, g_Vh, nullptr);
}

__global__ void __launch_bounds__(512, 1)
out_mma_kernel(const float* __restrict__ Wo, const float* __restrict__ bo,
               float* __restrict__ out)
{
    proj_gemm<0,1,1>(nullptr, g_att, Wo, bo, out, nullptr, nullptr);
}

// ---------------------------------------------------------------------------
// Flash attention. QK 2-term (Qh·K + Ql·K; Q exact, K single fp16);
// PV 1-term. 128 threads (4 warps x m32 = 128 q rows/CTA), 2 CTAs/SM.
// K + V single fp16, double-buffered via cp.async. Mask: query rows.
// ---------------------------------------------------------------------------
#define APAD 72
#define AQSLAB (128*APAD)                  // 9216 elems per Q slab
#define ASLAB  (64*APAD)                   // 4608 elems per KV slab
#define AKV0   (2*AQSLAB)
// KV slabs: [K0 K1 V0 V1]
#define ATT_SMEM ((2*AQSLAB + 4*ASLAB)*2)  // 73728 B -> 2 CTAs/SM

__global__ void __launch_bounds__(128, 2)
attn_mma_kernel(const int* __restrict__ mask)
{
    extern __shared__ __half sm[];
    const uint32_t sb = smem_u32(sm);
    const int tid  = threadIdx.x;
    const int lane = tid & 31;
    const int wid  = tid >> 5;             // 0..3
    const int g    = lane >> 2;
    const int cc   = lane & 3;

    const int bh = blockIdx.y;
    const int b  = bh >> 4;
    const int h  = bh & 15;
    const int q0 = blockIdx.x * 128;

    const __half* Qhi = g_Qh_hi + (size_t)bh*S_*DK_;
    const __half* Qlo = g_Qh_lo + (size_t)bh*S_*DK_;
    const __half* Kp  = g_Kh + (size_t)bh*S_*DK_;
    const __half* Vp  = g_Vh + (size_t)bh*S_*DK_;
    const int* mp = mask + b*S_;

    // ---- issue KV tile 0 via cp.async; load Q concurrently ----
    {
        #pragma unroll
        for (int i = 0; i < 4; i++) {
            const int idx = tid + i*128;           // 0..511
            const int row = idx >> 3, v = idx & 7;
            const uint32_t so = sb + 2*(AKV0 + row*APAD + v*8);
            const size_t  go = (size_t)row*DK_ + v*8;
            cpa16(so + 2*(0*ASLAB), Kp + go);
            cpa16(so + 2*(2*ASLAB), Vp + go);
        }
        CPA_COMMIT();
    }
    #pragma unroll
    for (int it = 0; it < 8; it++) {
        const int idx = tid + it*128;              // 0..1023
        const int row = idx >> 3, v = idx & 7;
        *(uint4*)(sm + 0      + row*APAD + v*8) =
            *((const uint4*)(Qhi + (size_t)(q0+row)*DK_) + v);
        *(uint4*)(sm + AQSLAB + row*APAD + v*8) =
            *((const uint4*)(Qlo + (size_t)(q0+row)*DK_) + v);
    }
    CPA_WAIT0();
    __syncthreads();

    const int qra0 = q0 + wid*32 + g;
    const int qra1 = qra0 + 16;
    bool msk[2][2];
    msk[0][0] = (mp[qra0] == 0);      msk[0][1] = (mp[qra0 + 8] == 0);
    msk[1][0] = (mp[qra1] == 0);      msk[1][1] = (mp[qra1 + 8] == 0);

    float mr[2][2], lr[2][2];
    #pragma unroll
    for (int mi = 0; mi < 2; mi++) { mr[mi][0] = mr[mi][1] = -1e30f; lr[mi][0] = lr[mi][1] = 0.0f; }

    float oacc[2][8][4];
    #pragma unroll
    for (int mi = 0; mi < 2; mi++)
        #pragma unroll
        for (int nj = 0; nj < 8; nj++)
            #pragma unroll
            for (int e = 0; e < 4; e++) oacc[mi][nj][e] = 0.0f;

    for (int t = 0; t < 32; t++) {
        const int cur = t & 1;
        const int nxt = cur ^ 1;
        const bool pf = (t + 1 < 32);
        const uint32_t k_u = sb + 2*(AKV0 + cur*ASLAB);
        const uint32_t v_u = sb + 2*(AKV0 + (2 + cur)*ASLAB);

        if (pf) {
            const size_t base = (size_t)((t + 1)*64)*DK_;
            #pragma unroll
            for (int i = 0; i < 4; i++) {
                const int idx = tid + i*128;
                const int row = idx >> 3, v = idx & 7;
                const uint32_t so = sb + 2*(AKV0 + row*APAD + v*8);
                const size_t  go = base + (size_t)row*DK_ + v*8;
                cpa16(so + 2*(nxt*ASLAB),       Kp + go);
                cpa16(so + 2*((2 + nxt)*ASLAB), Vp + go);
            }
            CPA_COMMIT();
        }

        // ---- S = Q K^T (2-term: Qh·K + Ql·K) ----
        float sacc[2][8][4];
        #pragma unroll
        for (int mi = 0; mi < 2; mi++)
            #pragma unroll
            for (int nj = 0; nj < 8; nj++)
                #pragma unroll
                for (int e = 0; e < 4; e++) sacc[mi][nj][e] = 0.0f;

        #pragma unroll
        for (int kk = 0; kk < 4; kk++) {
            uint32_t aqh[2][4], aql[2][4];
            #pragma unroll
            for (int mi = 0; mi < 2; mi++) {
                const int r   = wid*32 + mi*16 + (lane & 15);
                const int col = kk*16 + ((lane & 16) ? 8 : 0);
                ldsm4(aqh[mi], sb + 2*(0      + r*APAD + col));
                ldsm4(aql[mi], sb + 2*(AQSLAB + r*APAD + col));
            }
            #pragma unroll
            for (int jp = 0; jp < 4; jp++) {
                const int p   = lane >> 3;
                const int r   = jp*16 + ((p >= 2) ? 8 : 0) + (lane & 7);
                const int col = kk*16 + ((p & 1) ? 8 : 0);
                uint32_t th[4];
                ldsm4(th, k_u + 2*(r*APAD + col));
                #pragma unroll
                for (int mi = 0; mi < 2; mi++) {
                    mma16816(sacc[mi][2*jp],   aqh[mi], th);
                    mma16816(sacc[mi][2*jp],   aql[mi], th);
                    mma16816(sacc[mi][2*jp+1], aqh[mi], th+2);
                    mma16816(sacc[mi][2*jp+1], aql[mi], th+2);
                }
            }
        }

        // ---- mask + online softmax ----
        #pragma unroll
        for (int mi = 0; mi < 2; mi++) {
            if (msk[mi][0]) {
                #pragma unroll
                for (int nj = 0; nj < 8; nj++) { sacc[mi][nj][0] = NEGINF; sacc[mi][nj][1] = NEGINF; }
            }
            if (msk[mi][1]) {
                #pragma unroll
                for (int nj = 0; nj < 8; nj++) { sacc[mi][nj][2] = NEGINF; sacc[mi][nj][3] = NEGINF; }
            }

            float mx0 = -1e30f, mx1 = -1e30f;
            #pragma unroll
            for (int nj = 0; nj < 8; nj++) {
                mx0 = fmaxf(mx0, fmaxf(sacc[mi][nj][0], sacc[mi][nj][1]));
                mx1 = fmaxf(mx1, fmaxf(sacc[mi][nj][2], sacc[mi][nj][3]));
            }
            mx0 = fmaxf(mx0, __shfl_xor_sync(0xffffffffu, mx0, 1));
            mx0 = fmaxf(mx0, __shfl_xor_sync(0xffffffffu, mx0, 2));
            mx1 = fmaxf(mx1, __shfl_xor_sync(0xffffffffu, mx1, 1));
            mx1 = fmaxf(mx1, __shfl_xor_sync(0xffffffffu, mx1, 2));

            const float mn0 = fmaxf(mr[mi][0], mx0);
            const float mn1 = fmaxf(mr[mi][1], mx1);
            const float al0 = __expf(mr[mi][0] - mn0);
            const float al1 = __expf(mr[mi][1] - mn1);
            mr[mi][0] = mn0; mr[mi][1] = mn1;

            float rs0 = 0.0f, rs1 = 0.0f;
            #pragma unroll
            for (int nj = 0; nj < 8; nj++) {
                const float p0 = __expf(sacc[mi][nj][0] - mn0);
                const float p1 = __expf(sacc[mi][nj][1] - mn0);
                const float p2 = __expf(sacc[mi][nj][2] - mn1);
                const float p3 = __expf(sacc[mi][nj][3] - mn1);
                sacc[mi][nj][0] = p0; sacc[mi][nj][1] = p1;
                sacc[mi][nj][2] = p2; sacc[mi][nj][3] = p3;
                rs0 += p0 + p1; rs1 += p2 + p3;
            }
            rs0 += __shfl_xor_sync(0xffffffffu, rs0, 1);
            rs0 += __shfl_xor_sync(0xffffffffu, rs0, 2);
            rs1 += __shfl_xor_sync(0xffffffffu, rs1, 1);
            rs1 += __shfl_xor_sync(0xffffffffu, rs1, 2);
            lr[mi][0] = lr[mi][0]*al0 + rs0;
            lr[mi][1] = lr[mi][1]*al1 + rs1;

            #pragma unroll
            for (int nj = 0; nj < 8; nj++) {
                oacc[mi][nj][0] *= al0; oacc[mi][nj][1] *= al0;
                oacc[mi][nj][2] *= al1; oacc[mi][nj][3] *= al1;
            }
        }

        // ---- O += P V (1-term) ----
        #pragma unroll
        for (int t4 = 0; t4 < 4; t4++) {
            uint32_t pa[2][4];
            #pragma unroll
            for (int mi = 0; mi < 2; mi++) {
                pa[mi][0] = packh(sacc[mi][2*t4][0],   sacc[mi][2*t4][1]);
                pa[mi][1] = packh(sacc[mi][2*t4][2],   sacc[mi][2*t4][3]);
                pa[mi][2] = packh(sacc[mi][2*t4+1][0], sacc[mi][2*t4+1][1]);
                pa[mi][3] = packh(sacc[mi][2*t4+1][2], sacc[mi][2*t4+1][3]);
            }
            #pragma unroll
            for (int jp = 0; jp < 4; jp++) {
                const int p   = lane >> 3;
                const int r   = t4*16 + ((p & 1) ? 8 : 0) + (lane & 7);
                const int col = jp*16 + ((p >= 2) ? 8 : 0);
                uint32_t th[4];
                ldsm4_t(th, v_u + 2*(r*APAD + col));
                #pragma unroll
                for (int mi = 0; mi < 2; mi++) {
                    mma16816(oacc[mi][2*jp],   pa[mi], th);
                    mma16816(oacc[mi][2*jp+1], pa[mi], th+2);
                }
            }
        }

        if (pf) CPA_WAIT0();
        __syncthreads();
    }

    // ---- epilogue: att = oacc / l -> single fp16 concat [b,s,h*64+dk] ----
    #pragma unroll
    for (int mi = 0; mi < 2; mi++) {
        const int qa = (mi == 0) ? qra0 : qra1;
        const float inv0 = 1.0f / lr[mi][0];
        const float inv1 = 1.0f / lr[mi][1];
        const size_t basea = ((size_t)(b*S_ + qa))*D_ + h*DK_;
        const size_t baseb = ((size_t)(b*S_ + qa + 8))*D_ + h*DK_;
        #pragma unroll
        for (int nj = 0; nj < 8; nj++) {
            const int dk = nj*8 + cc*2;
            *(uint32_t*)&g_att[basea + dk] = packh(oacc[mi][nj][0]*inv0, oacc[mi][nj][1]*inv0);
            *(uint32_t*)&g_att[baseb + dk] = packh(oacc[mi][nj][2]*inv1, oacc[mi][nj][3]*inv1);
        }
    }
}

// ---------------------------------------------------------------------------
extern "C" void kernel_launch(void* const* d_in, const int* in_sizes, int n_in,
                              void* d_out, int out_size)
{
    const float* q    = (const float*)d_in[0];
    const float* k    = (const float*)d_in[1];
    const float* v    = (const float*)d_in[2];
    const int*   mask = (const int*)  d_in[3];
    const float* Wq   = (const float*)d_in[4];
    const float* bq   = (const float*)d_in[5];
    const float* Wk   = (const float*)d_in[6];
    const float* bk   = (const float*)d_in[7];
    const float* Wv   = (const float*)d_in[8];
    const float* bv   = (const float*)d_in[9];
    const float* Wo   = (const float*)d_in[10];
    const float* bo   = (const float*)d_in[11];
    float* out = (float*)d_out;

    static int configured = 0;
    if (!configured) {
        cudaFuncSetAttribute(qkv_mma_kernel, cudaFuncAttributeMaxDynamicSharedMemorySize, PROJ_SMEM3);
        cudaFuncSetAttribute(out_mma_kernel, cudaFuncAttributeMaxDynamicSharedMemorySize, PROJ_SMEM1);
        cudaFuncSetAttribute(attn_mma_kernel, cudaFuncAttributeMaxDynamicSharedMemorySize, ATT_SMEM);
        configured = 1;
    }

    // 1. QKV projections: Q 3-term (hi/lo out), K 2-term (single out), V 1-term
    qkv_mma_kernel<<<dim3(D_/256, M_/128, 3), 512, PROJ_SMEM3>>>(
        q, k, v, Wq, bq, Wk, bk, Wv, bv);

    // 2. Attention: QK 2-term, PV 1-term; 4-warp CTAs, 2 CTAs/SM
    attn_mma_kernel<<<dim3(S_/128, B_*H_), 128, ATT_SMEM>>>(mask);

    // 3. Output projection: 1-term
    out_mma_kernel<<<dim3(D_/256, M_/128), 512, PROJ_SMEM1>>>(Wo, bo, out);
}